// round 3
// baseline (speedup 1.0000x reference)
#include <cuda_runtime.h>
#include <cuda_bf16.h>
#include <math.h>

#define Bv 2
#define Sv 2048
#define Ev 1024
#define Hv 16
#define Dv 64
#define Mv (Bv*Sv)   // 4096

// Scratch (allocation-free rule: device globals)
__device__ float g_q[(size_t)Bv*Hv*Sv*Dv];
__device__ float g_k[(size_t)Bv*Hv*Sv*Dv];
__device__ float g_v[(size_t)Bv*Hv*Sv*Dv];
__device__ float g_ctx[(size_t)Bv*Sv*Ev];

// ---------------------------------------------------------------------------
// Fused QKV projection: one launch, blockIdx.z = 0/1/2 (Q/K/V).
// C[M,N] = X[M,K] * W[N,K]^T + bias, written to head layout [B,H,S,D].
// Software-pipelined: next k-tile prefetched into registers during compute.
// ---------------------------------------------------------------------------
__global__ __launch_bounds__(256)
void gemm_qkv(const float* __restrict__ Xq,
              const float* __restrict__ Xk,
              const float* __restrict__ Xv,
              const float* __restrict__ qkvw,
              const float* __restrict__ qkvb)
{
    const int K = Ev;
    __shared__ float sA[16][128];
    __shared__ float sB[16][128];

    int z = blockIdx.z;
    const float* Ain  = (z == 0) ? Xq : (z == 1) ? Xk : Xv;
    const float* W    = qkvw + (size_t)z * Ev * Ev;
    const float* bias = qkvb + (size_t)z * Ev;
    float* out        = (z == 0) ? g_q : (z == 1) ? g_k : g_v;

    int t  = threadIdx.x;
    int tx = t & 15, ty = t >> 4;
    int m0 = blockIdx.y * 128, n0 = blockIdx.x * 128;
    int lr = t >> 2;            // 0..63
    int lc = (t & 3) << 2;      // 0,4,8,12

    float acc[8][8];
#pragma unroll
    for (int i = 0; i < 8; i++)
#pragma unroll
        for (int j = 0; j < 8; j++) acc[i][j] = 0.f;

    float4 pa[2], pb[2];
#pragma unroll
    for (int h = 0; h < 2; h++) {
        int row = lr + h * 64;
        pa[h] = *(const float4*)(Ain + (size_t)(m0 + row) * K + lc);
        pb[h] = *(const float4*)(W   + (size_t)(n0 + row) * K + lc);
    }

    for (int k0 = 0; k0 < K; k0 += 16) {
        __syncthreads();
#pragma unroll
        for (int h = 0; h < 2; h++) {
            int row = lr + h * 64;
            sA[lc + 0][row] = pa[h].x; sA[lc + 1][row] = pa[h].y;
            sA[lc + 2][row] = pa[h].z; sA[lc + 3][row] = pa[h].w;
            sB[lc + 0][row] = pb[h].x; sB[lc + 1][row] = pb[h].y;
            sB[lc + 2][row] = pb[h].z; sB[lc + 3][row] = pb[h].w;
        }
        __syncthreads();

        if (k0 + 16 < K) {
#pragma unroll
            for (int h = 0; h < 2; h++) {
                int row = lr + h * 64;
                pa[h] = *(const float4*)(Ain + (size_t)(m0 + row) * K + k0 + 16 + lc);
                pb[h] = *(const float4*)(W   + (size_t)(n0 + row) * K + k0 + 16 + lc);
            }
        }

#pragma unroll
        for (int kk = 0; kk < 16; kk++) {
            float4 a0 = *(const float4*)&sA[kk][ty * 8];
            float4 a1 = *(const float4*)&sA[kk][ty * 8 + 4];
            float4 b0 = *(const float4*)&sB[kk][tx * 8];
            float4 b1 = *(const float4*)&sB[kk][tx * 8 + 4];
            float ra[8] = {a0.x, a0.y, a0.z, a0.w, a1.x, a1.y, a1.z, a1.w};
            float rb[8] = {b0.x, b0.y, b0.z, b0.w, b1.x, b1.y, b1.z, b1.w};
#pragma unroll
            for (int i = 0; i < 8; i++)
#pragma unroll
                for (int j = 0; j < 8; j++)
                    acc[i][j] = fmaf(ra[i], rb[j], acc[i][j]);
        }
    }

    float rbias[8];
#pragma unroll
    for (int j = 0; j < 8; j++) rbias[j] = bias[n0 + tx * 8 + j];

#pragma unroll
    for (int i = 0; i < 8; i++) {
        int m = m0 + ty * 8 + i;
        int b = m / Sv, s = m % Sv;
#pragma unroll
        for (int j = 0; j < 8; j++) {
            float v = acc[i][j] + rbias[j];
            int f = n0 + tx * 8 + j;
            int hh = f >> 6, d = f & 63;
            out[(((size_t)b * Hv + hh) * Sv + s) * Dv + d] = v;
        }
    }
}

// ---------------------------------------------------------------------------
// Output projection: out[M,E] = g_ctx[M,E] * projw[E,E]^T + projb
// ---------------------------------------------------------------------------
__global__ __launch_bounds__(256)
void gemm_proj(const float* __restrict__ W,
               const float* __restrict__ bias,
               float* __restrict__ out)
{
    const int K = Ev;
    __shared__ float sA[16][128];
    __shared__ float sB[16][128];

    const float* Ain = g_ctx;

    int t  = threadIdx.x;
    int tx = t & 15, ty = t >> 4;
    int m0 = blockIdx.y * 128, n0 = blockIdx.x * 128;
    int lr = t >> 2;
    int lc = (t & 3) << 2;

    float acc[8][8];
#pragma unroll
    for (int i = 0; i < 8; i++)
#pragma unroll
        for (int j = 0; j < 8; j++) acc[i][j] = 0.f;

    float4 pa[2], pb[2];
#pragma unroll
    for (int h = 0; h < 2; h++) {
        int row = lr + h * 64;
        pa[h] = *(const float4*)(Ain + (size_t)(m0 + row) * K + lc);
        pb[h] = *(const float4*)(W   + (size_t)(n0 + row) * K + lc);
    }

    for (int k0 = 0; k0 < K; k0 += 16) {
        __syncthreads();
#pragma unroll
        for (int h = 0; h < 2; h++) {
            int row = lr + h * 64;
            sA[lc + 0][row] = pa[h].x; sA[lc + 1][row] = pa[h].y;
            sA[lc + 2][row] = pa[h].z; sA[lc + 3][row] = pa[h].w;
            sB[lc + 0][row] = pb[h].x; sB[lc + 1][row] = pb[h].y;
            sB[lc + 2][row] = pb[h].z; sB[lc + 3][row] = pb[h].w;
        }
        __syncthreads();

        if (k0 + 16 < K) {
#pragma unroll
            for (int h = 0; h < 2; h++) {
                int row = lr + h * 64;
                pa[h] = *(const float4*)(Ain + (size_t)(m0 + row) * K + k0 + 16 + lc);
                pb[h] = *(const float4*)(W   + (size_t)(n0 + row) * K + k0 + 16 + lc);
            }
        }

#pragma unroll
        for (int kk = 0; kk < 16; kk++) {
            float4 a0 = *(const float4*)&sA[kk][ty * 8];
            float4 a1 = *(const float4*)&sA[kk][ty * 8 + 4];
            float4 b0 = *(const float4*)&sB[kk][tx * 8];
            float4 b1 = *(const float4*)&sB[kk][tx * 8 + 4];
            float ra[8] = {a0.x, a0.y, a0.z, a0.w, a1.x, a1.y, a1.z, a1.w};
            float rb[8] = {b0.x, b0.y, b0.z, b0.w, b1.x, b1.y, b1.z, b1.w};
#pragma unroll
            for (int i = 0; i < 8; i++)
#pragma unroll
                for (int j = 0; j < 8; j++)
                    acc[i][j] = fmaf(ra[i], rb[j], acc[i][j]);
        }
    }

    float rbias[8];
#pragma unroll
    for (int j = 0; j < 8; j++) rbias[j] = bias[n0 + tx * 8 + j];

#pragma unroll
    for (int i = 0; i < 8; i++) {
        int m = m0 + ty * 8 + i;
#pragma unroll
        for (int j = 0; j < 8; j++)
            out[(size_t)m * Ev + n0 + tx * 8 + j] = acc[i][j] + rbias[j];
    }
}

// ---------------------------------------------------------------------------
// Flash attention: per block = one (b, h, 64-row q tile).
// sQ[64][64] natural; sKP: K^T stride 65 (score phase) then P stride 64;
// sV[64][64] natural. Online softmax, stats via 16-lane shfl reductions.
// ---------------------------------------------------------------------------
__global__ __launch_bounds__(256)
void attn_kernel(const float* __restrict__ mask)
{
    extern __shared__ float sm[];
    float* sQ  = sm;                  // 64*64
    float* sKP = sm + 64 * 64;        // 64*65 (K^T) / 64*64 (P)
    float* sV  = sKP + 64 * 65;       // 64*64

    int t  = threadIdx.x;
    int tx = t & 15, ty = t >> 4;
    int qt = blockIdx.x;
    int h  = blockIdx.y;
    int b  = blockIdx.z;
    int bh = b * Hv + h;
    size_t base = (size_t)bh * Sv * Dv;
    int q0 = qt * 64;

    // Load Q tile (coalesced float4)
#pragma unroll
    for (int p = 0; p < 4; p++) {
        int fidx = p * 256 + t;          // 1024 float4s
        int r = fidx >> 4;
        int c4 = (fidx & 15) << 2;
        *(float4*)&sQ[r * 64 + c4] =
            *(const float4*)&g_q[base + (size_t)(q0 + r) * 64 + c4];
    }

    float m_i[4], l_i[4], ctx[4][4];
#pragma unroll
    for (int i = 0; i < 4; i++) {
        m_i[i] = -1e30f; l_i[i] = 0.f;
#pragma unroll
        for (int j = 0; j < 4; j++) ctx[i][j] = 0.f;
    }

    const float scale = 0.125f;  // 1/sqrt(64)

    for (int kt = 0; kt < Sv / 64; kt++) {
        int kv0 = kt * 64;
        __syncthreads();   // previous iter done with sKP(P) and sV
        // Load K transposed (stride 65) + V natural — coalesced global reads
#pragma unroll
        for (int p = 0; p < 4; p++) {
            int fidx = p * 256 + t;
            int c  = fidx >> 4;
            int d4 = (fidx & 15) << 2;
            float4 k4 = *(const float4*)&g_k[base + (size_t)(kv0 + c) * 64 + d4];
            sKP[(d4 + 0) * 65 + c] = k4.x;
            sKP[(d4 + 1) * 65 + c] = k4.y;
            sKP[(d4 + 2) * 65 + c] = k4.z;
            sKP[(d4 + 3) * 65 + c] = k4.w;
            *(float4*)&sV[c * 64 + d4] =
                *(const float4*)&g_v[base + (size_t)(kv0 + c) * 64 + d4];
        }
        __syncthreads();

        // Scores: S = Q * K^T  (thread owns 4 rows x 4 cols)
        float s[4][4];
#pragma unroll
        for (int i = 0; i < 4; i++)
#pragma unroll
            for (int j = 0; j < 4; j++) s[i][j] = 0.f;

#pragma unroll 4
        for (int d = 0; d < 64; d++) {
            float qv[4], kv[4];
#pragma unroll
            for (int i = 0; i < 4; i++) qv[i] = sQ[(ty * 4 + i) * 64 + d];
#pragma unroll
            for (int j = 0; j < 4; j++) kv[j] = sKP[d * 65 + tx * 4 + j];
#pragma unroll
            for (int i = 0; i < 4; i++)
#pragma unroll
                for (int j = 0; j < 4; j++)
                    s[i][j] = fmaf(qv[i], kv[j], s[i][j]);
        }

        // scale + additive mask
#pragma unroll
        for (int i = 0; i < 4; i++) {
            const float* mrow = mask + (size_t)(q0 + ty * 4 + i) * Sv + kv0;
#pragma unroll
            for (int j = 0; j < 4; j++)
                s[i][j] = fmaf(s[i][j], scale, mrow[tx * 4 + j]);
        }

        // Online softmax update
#pragma unroll
        for (int i = 0; i < 4; i++) {
            float mt = fmaxf(fmaxf(s[i][0], s[i][1]), fmaxf(s[i][2], s[i][3]));
#pragma unroll
            for (int o = 8; o >= 1; o >>= 1)
                mt = fmaxf(mt, __shfl_xor_sync(0xffffffffu, mt, o, 16));
            float mn = fmaxf(m_i[i], mt);
            float alpha = __expf(m_i[i] - mn);
            m_i[i] = mn;
            float ls = 0.f;
#pragma unroll
            for (int j = 0; j < 4; j++) {
                s[i][j] = __expf(s[i][j] - mn);
                ls += s[i][j];
            }
#pragma unroll
            for (int o = 8; o >= 1; o >>= 1)
                ls += __shfl_xor_sync(0xffffffffu, ls, o, 16);
            l_i[i] = l_i[i] * alpha + ls;
#pragma unroll
            for (int j = 0; j < 4; j++) ctx[i][j] *= alpha;
        }

        __syncthreads();   // all threads done reading K from sKP
        // Write P (stride 64, float4 — conflict free)
#pragma unroll
        for (int i = 0; i < 4; i++)
            *(float4*)&sKP[(ty * 4 + i) * 64 + tx * 4] =
                make_float4(s[i][0], s[i][1], s[i][2], s[i][3]);
        __syncthreads();

        // ctx += P * V  (thread owns 4 rows x 4 dims, dims = tx*4..+3)
#pragma unroll 4
        for (int c = 0; c < 64; c++) {
            float pv[4];
#pragma unroll
            for (int i = 0; i < 4; i++) pv[i] = sKP[(ty * 4 + i) * 64 + c];
            float4 v4 = *(const float4*)&sV[c * 64 + tx * 4];
#pragma unroll
            for (int i = 0; i < 4; i++) {
                ctx[i][0] = fmaf(pv[i], v4.x, ctx[i][0]);
                ctx[i][1] = fmaf(pv[i], v4.y, ctx[i][1]);
                ctx[i][2] = fmaf(pv[i], v4.z, ctx[i][2]);
                ctx[i][3] = fmaf(pv[i], v4.w, ctx[i][3]);
            }
        }
    }

    // Normalize and write ctx in [B,S,E] layout
#pragma unroll
    for (int i = 0; i < 4; i++) {
        float invl = 1.f / l_i[i];
        int srow = q0 + ty * 4 + i;
        float4 o4 = make_float4(ctx[i][0] * invl, ctx[i][1] * invl,
                                ctx[i][2] * invl, ctx[i][3] * invl);
        *(float4*)&g_ctx[((size_t)b * Sv + srow) * Ev + h * 64 + tx * 4] = o4;
    }
}

// ---------------------------------------------------------------------------
extern "C" void kernel_launch(void* const* d_in, const int* in_sizes, int n_in,
                              void* d_out, int out_size)
{
    const float* query = (const float*)d_in[0];
    const float* key   = (const float*)d_in[1];
    const float* value = (const float*)d_in[2];
    const float* qkvw  = (const float*)d_in[3];
    const float* qkvb  = (const float*)d_in[4];
    const float* projw = (const float*)d_in[5];
    const float* projb = (const float*)d_in[6];
    const float* mask  = (const float*)d_in[7];
    float* out = (float*)d_out;

    dim3 blk(256);

    gemm_qkv<<<dim3(Ev / 128, Mv / 128, 3), blk>>>(query, key, value, qkvw, qkvb);

    size_t smem = (size_t)(64 * 64 + 64 * 65 + 64 * 64) * sizeof(float); // 49,408 B
    cudaFuncSetAttribute(attn_kernel,
                         cudaFuncAttributeMaxDynamicSharedMemorySize, (int)smem);
    attn_kernel<<<dim3(Sv / 64, Hv, Bv), blk, smem>>>(mask);

    gemm_proj<<<dim3(Ev / 128, Mv / 128), blk>>>(projw, projb, out);
}

// round 14
// speedup vs baseline: 1.4648x; 1.4648x over previous
#include <cuda_runtime.h>
#include <cuda_bf16.h>
#include <stdint.h>
#include <math.h>

#define Bv 2
#define Sv 2048
#define Ev 1024
#define Hv 16
#define Dv 64
#define Mv (Bv*Sv)   // 4096

#define TM 128
#define TN 128
#define KC 32                 // bf16 K elements per smem chunk
#define NCH (Ev/KC)           // 32 chunks
#define KCP 40                // padded row stride (bf16) -> conflict-free frags
#define TSZ (128*KCP)         // bf16 units per tile
#define BSZ (4*TSZ)           // bf16 units per buffer (Ah,Al,Bh,Bl)

// ---------------- scratch (device globals; no allocs allowed) ----------------
__device__ float g_q[(size_t)Bv*Hv*Sv*Dv];
__device__ float g_k[(size_t)Bv*Hv*Sv*Dv];
__device__ float g_v[(size_t)Bv*Hv*Sv*Dv];
__device__ __nv_bfloat16 g_xh[(size_t)3*Mv*Ev], g_xl[(size_t)3*Mv*Ev];     // q,k,v inputs hi/lo
__device__ __nv_bfloat16 g_wqh[(size_t)3*Ev*Ev], g_wql[(size_t)3*Ev*Ev];   // qkv weight hi/lo
__device__ __nv_bfloat16 g_wph[(size_t)Ev*Ev],  g_wpl[(size_t)Ev*Ev];      // proj weight hi/lo
__device__ __nv_bfloat16 g_ctxh[(size_t)Mv*Ev], g_ctxl[(size_t)Mv*Ev];     // attention output hi/lo

// ---------------- PTX helpers (baseline sm_80+ features ONLY) ----------------
__device__ __forceinline__ uint32_t s2u(const void* p) {
    uint32_t a;
    asm("{ .reg .u64 t; cvta.to.shared.u64 t, %1; cvt.u32.u64 %0, t; }" : "=r"(a) : "l"(p));
    return a;
}
__device__ __forceinline__ void cpa16(uint32_t saddr, const void* gaddr) {
    asm volatile("cp.async.cg.shared.global [%0], [%1], 16;" :: "r"(saddr), "l"(gaddr));
}
#define CP_COMMIT() asm volatile("cp.async.commit_group;" ::: "memory")
#define CP_WAIT1()  asm volatile("cp.async.wait_group 1;" ::: "memory")
#define CP_WAIT0()  asm volatile("cp.async.wait_group 0;" ::: "memory")

// D += A*B  (m16n8k16, bf16 in, fp32 accum; accumulate in place)
#define MMA4(d, a, b) \
    asm volatile("mma.sync.aligned.m16n8k16.row.col.f32.bf16.bf16.f32 " \
        "{%0,%1,%2,%3}, {%4,%5,%6,%7}, {%8,%9}, {%0,%1,%2,%3};" \
        : "+f"((d)[0]), "+f"((d)[1]), "+f"((d)[2]), "+f"((d)[3]) \
        : "r"((a)[0]), "r"((a)[1]), "r"((a)[2]), "r"((a)[3]), \
          "r"((b)[0]), "r"((b)[1]))

// ---------------- fp32 -> bf16 hi/lo split pre-pass ----------------
__global__ __launch_bounds__(256)
void split_bf16(const float4* __restrict__ x, int dst, int n4)
{
    int i = blockIdx.x * 256 + threadIdx.x;
    if (i >= n4) return;
    __nv_bfloat16 *hi, *lo;
    if (dst < 3)      { hi = g_xh + (size_t)dst * Mv * Ev; lo = g_xl + (size_t)dst * Mv * Ev; }
    else if (dst == 3){ hi = g_wqh; lo = g_wql; }
    else              { hi = g_wph; lo = g_wpl; }
    float4 v = x[i];
    union { __nv_bfloat16 b[4]; uint2 u; } uh, ul;
    float f[4] = {v.x, v.y, v.z, v.w};
#pragma unroll
    for (int j = 0; j < 4; j++) {
        uh.b[j] = __float2bfloat16(f[j]);
        ul.b[j] = __float2bfloat16(f[j] - __bfloat162float(uh.b[j]));
    }
    ((uint2*)hi)[i] = uh.u;
    ((uint2*)lo)[i] = ul.u;
}

// ---------------- HMMA GEMM: C = A*W^T + bias, hi/lo 3-term bf16 -------------
// MODE 0: QKV (blockIdx.z selects q/k/v), writes g_q/g_k/g_v in [B,H,S,D]
// MODE 1: proj, A = g_ctx hi/lo, writes out[M,E]
template<int MODE>
__global__ __launch_bounds__(256)
void gemm_mma(const float* __restrict__ bias_all, float* __restrict__ out_param)
{
    extern __shared__ __nv_bfloat16 smb[];

    int t = threadIdx.x, wid = t >> 5, lane = t & 31;
    int gid = lane >> 2, tig = lane & 3;     // mma group row / pair col
    int wm = wid >> 2, wn = wid & 3;         // 2 x 4 warp grid
    int n0 = blockIdx.x * TN, m0 = blockIdx.y * TM;
    int z = blockIdx.z;

    const __nv_bfloat16 *Ah, *Al, *Bh, *Bl;
    const float* bias;
    if (MODE == 0) {
        Ah = g_xh + (size_t)z * Mv * Ev;  Al = g_xl + (size_t)z * Mv * Ev;
        Bh = g_wqh + (size_t)z * Ev * Ev; Bl = g_wql + (size_t)z * Ev * Ev;
        bias = bias_all + (size_t)z * Ev;
    } else {
        Ah = g_ctxh; Al = g_ctxl; Bh = g_wph; Bl = g_wpl;
        bias = bias_all;
    }

    uint32_t smem_u = s2u(smb);

    float acc[4][4][4];
#pragma unroll
    for (int mi = 0; mi < 4; mi++)
#pragma unroll
        for (int ni = 0; ni < 4; ni++)
#pragma unroll
            for (int r = 0; r < 4; r++) acc[mi][ni][r] = 0.f;

    // cp.async one chunk (4 tiles of 128 rows x KC bf16) into buffer b
    auto ISSUE = [&](int b, int c) {
        int k0 = c * KC;
        const __nv_bfloat16* gs[4] = {Ah, Al, Bh, Bl};
        int r0[4] = {m0, m0, n0, n0};
#pragma unroll
        for (int tt = 0; tt < 4; tt++) {
            uint32_t sb = smem_u + (uint32_t)(b * BSZ + tt * TSZ) * 2;
#pragma unroll
            for (int p = 0; p < 2; p++) {
                int idx = t + p * 256;            // 512 x 16B per tile
                int row = idx >> 2, seg = idx & 3;
                cpa16(sb + row * (KCP * 2) + seg * 16,
                      gs[tt] + (size_t)(r0[tt] + row) * Ev + k0 + seg * 8);
            }
        }
    };

    // Consume one chunk from buffer b: 2 k16 steps x 3 compensation terms
    auto COMPUTE = [&](int b) {
        const __nv_bfloat16* TAh = smb + b * BSZ;
        const __nv_bfloat16* TAl = TAh + TSZ;
        const __nv_bfloat16* TBh = TAl + TSZ;
        const __nv_bfloat16* TBl = TBh + TSZ;
#pragma unroll
        for (int ks = 0; ks < 2; ks++) {
            int kb = ks * 16 + tig * 2;
            uint32_t ah[4][4], al[4][4], bh[4][2], bl[4][2];
#pragma unroll
            for (int mi = 0; mi < 4; mi++) {
                int r = wm * 64 + mi * 16 + gid;
                ah[mi][0] = *(const uint32_t*)&TAh[r * KCP + kb];
                ah[mi][1] = *(const uint32_t*)&TAh[(r + 8) * KCP + kb];
                ah[mi][2] = *(const uint32_t*)&TAh[r * KCP + kb + 8];
                ah[mi][3] = *(const uint32_t*)&TAh[(r + 8) * KCP + kb + 8];
                al[mi][0] = *(const uint32_t*)&TAl[r * KCP + kb];
                al[mi][1] = *(const uint32_t*)&TAl[(r + 8) * KCP + kb];
                al[mi][2] = *(const uint32_t*)&TAl[r * KCP + kb + 8];
                al[mi][3] = *(const uint32_t*)&TAl[(r + 8) * KCP + kb + 8];
            }
#pragma unroll
            for (int ni = 0; ni < 4; ni++) {
                int r = wn * 32 + ni * 8 + gid;
                bh[ni][0] = *(const uint32_t*)&TBh[r * KCP + kb];
                bh[ni][1] = *(const uint32_t*)&TBh[r * KCP + kb + 8];
                bl[ni][0] = *(const uint32_t*)&TBl[r * KCP + kb];
                bl[ni][1] = *(const uint32_t*)&TBl[r * KCP + kb + 8];
            }
#pragma unroll
            for (int mi = 0; mi < 4; mi++)
#pragma unroll
                for (int ni = 0; ni < 4; ni++) {
                    MMA4(acc[mi][ni], ah[mi], bh[ni]);
                    MMA4(acc[mi][ni], ah[mi], bl[ni]);
                    MMA4(acc[mi][ni], al[mi], bh[ni]);
                }
        }
    };

    ISSUE(0, 0); CP_COMMIT();
    for (int c = 0; c < NCH; c++) {
        if (c + 1 < NCH) { ISSUE((c + 1) & 1, c + 1); CP_COMMIT(); CP_WAIT1(); }
        else             { CP_WAIT0(); }
        __syncthreads();
        COMPUTE(c & 1);
        __syncthreads();
    }

    // Epilogue: d0/d1 -> row mA, d2/d3 -> row mA+8; cols f, f+1
#pragma unroll
    for (int mi = 0; mi < 4; mi++) {
        int mA = m0 + wm * 64 + mi * 16 + gid;
        int mB = mA + 8;
#pragma unroll
        for (int ni = 0; ni < 4; ni++) {
            int f = n0 + wn * 32 + ni * 8 + tig * 2;
            float b0 = bias[f], b1 = bias[f + 1];
            float2 v0 = make_float2(acc[mi][ni][0] + b0, acc[mi][ni][1] + b1);
            float2 v1 = make_float2(acc[mi][ni][2] + b0, acc[mi][ni][3] + b1);
            if (MODE == 0) {
                float* outp = (z == 0) ? g_q : (z == 1) ? g_k : g_v;
                int hh = f >> 6, d = f & 63;
                int bA = mA >> 11, sA = mA & (Sv - 1);
                int bB = mB >> 11, sB = mB & (Sv - 1);
                *(float2*)&outp[(((size_t)bA * Hv + hh) * Sv + sA) * Dv + d] = v0;
                *(float2*)&outp[(((size_t)bB * Hv + hh) * Sv + sB) * Dv + d] = v1;
            } else {
                *(float2*)&out_param[(size_t)mA * Ev + f] = v0;
                *(float2*)&out_param[(size_t)mB * Ev + f] = v1;
            }
        }
    }
}

// ---------------------------------------------------------------------------
// Flash attention (fp32 SIMT, unchanged math). Epilogue writes ctx as
// bf16 hi/lo for the HMMA proj GEMM.
// ---------------------------------------------------------------------------
__global__ __launch_bounds__(256)
void attn_kernel(const float* __restrict__ mask)
{
    extern __shared__ float sm[];
    float* sQ  = sm;                  // 64*64
    float* sKP = sm + 64 * 64;        // 64*65 (K^T) / 64*64 (P)
    float* sV  = sKP + 64 * 65;       // 64*64

    int t  = threadIdx.x;
    int tx = t & 15, ty = t >> 4;
    int qt = blockIdx.x;
    int h  = blockIdx.y;
    int b  = blockIdx.z;
    int bh = b * Hv + h;
    size_t base = (size_t)bh * Sv * Dv;
    int q0 = qt * 64;

#pragma unroll
    for (int p = 0; p < 4; p++) {
        int fidx = p * 256 + t;
        int r = fidx >> 4;
        int c4 = (fidx & 15) << 2;
        *(float4*)&sQ[r * 64 + c4] =
            *(const float4*)&g_q[base + (size_t)(q0 + r) * 64 + c4];
    }

    float m_i[4], l_i[4], ctx[4][4];
#pragma unroll
    for (int i = 0; i < 4; i++) {
        m_i[i] = -1e30f; l_i[i] = 0.f;
#pragma unroll
        for (int j = 0; j < 4; j++) ctx[i][j] = 0.f;
    }

    const float scale = 0.125f;

    for (int kt = 0; kt < Sv / 64; kt++) {
        int kv0 = kt * 64;
        __syncthreads();
#pragma unroll
        for (int p = 0; p < 4; p++) {
            int fidx = p * 256 + t;
            int c  = fidx >> 4;
            int d4 = (fidx & 15) << 2;
            float4 k4 = *(const float4*)&g_k[base + (size_t)(kv0 + c) * 64 + d4];
            sKP[(d4 + 0) * 65 + c] = k4.x;
            sKP[(d4 + 1) * 65 + c] = k4.y;
            sKP[(d4 + 2) * 65 + c] = k4.z;
            sKP[(d4 + 3) * 65 + c] = k4.w;
            *(float4*)&sV[c * 64 + d4] =
                *(const float4*)&g_v[base + (size_t)(kv0 + c) * 64 + d4];
        }
        __syncthreads();

        float s[4][4];
#pragma unroll
        for (int i = 0; i < 4; i++)
#pragma unroll
            for (int j = 0; j < 4; j++) s[i][j] = 0.f;

#pragma unroll 4
        for (int d = 0; d < 64; d++) {
            float qv[4], kv[4];
#pragma unroll
            for (int i = 0; i < 4; i++) qv[i] = sQ[(ty * 4 + i) * 64 + d];
#pragma unroll
            for (int j = 0; j < 4; j++) kv[j] = sKP[d * 65 + tx * 4 + j];
#pragma unroll
            for (int i = 0; i < 4; i++)
#pragma unroll
                for (int j = 0; j < 4; j++)
                    s[i][j] = fmaf(qv[i], kv[j], s[i][j]);
        }

#pragma unroll
        for (int i = 0; i < 4; i++) {
            const float* mrow = mask + (size_t)(q0 + ty * 4 + i) * Sv + kv0;
#pragma unroll
            for (int j = 0; j < 4; j++)
                s[i][j] = fmaf(s[i][j], scale, mrow[tx * 4 + j]);
        }

#pragma unroll
        for (int i = 0; i < 4; i++) {
            float mt = fmaxf(fmaxf(s[i][0], s[i][1]), fmaxf(s[i][2], s[i][3]));
#pragma unroll
            for (int o = 8; o >= 1; o >>= 1)
                mt = fmaxf(mt, __shfl_xor_sync(0xffffffffu, mt, o, 16));
            float mn = fmaxf(m_i[i], mt);
            float alpha = __expf(m_i[i] - mn);
            m_i[i] = mn;
            float ls = 0.f;
#pragma unroll
            for (int j = 0; j < 4; j++) {
                s[i][j] = __expf(s[i][j] - mn);
                ls += s[i][j];
            }
#pragma unroll
            for (int o = 8; o >= 1; o >>= 1)
                ls += __shfl_xor_sync(0xffffffffu, ls, o, 16);
            l_i[i] = l_i[i] * alpha + ls;
#pragma unroll
            for (int j = 0; j < 4; j++) ctx[i][j] *= alpha;
        }

        __syncthreads();
#pragma unroll
        for (int i = 0; i < 4; i++)
            *(float4*)&sKP[(ty * 4 + i) * 64 + tx * 4] =
                make_float4(s[i][0], s[i][1], s[i][2], s[i][3]);
        __syncthreads();

#pragma unroll 4
        for (int c = 0; c < 64; c++) {
            float pv[4];
#pragma unroll
            for (int i = 0; i < 4; i++) pv[i] = sKP[(ty * 4 + i) * 64 + c];
            float4 v4 = *(const float4*)&sV[c * 64 + tx * 4];
#pragma unroll
            for (int i = 0; i < 4; i++) {
                ctx[i][0] = fmaf(pv[i], v4.x, ctx[i][0]);
                ctx[i][1] = fmaf(pv[i], v4.y, ctx[i][1]);
                ctx[i][2] = fmaf(pv[i], v4.z, ctx[i][2]);
                ctx[i][3] = fmaf(pv[i], v4.w, ctx[i][3]);
            }
        }
    }

    // Normalize and write ctx as bf16 hi/lo in [B,S,E] layout
#pragma unroll
    for (int i = 0; i < 4; i++) {
        float invl = 1.f / l_i[i];
        int srow = q0 + ty * 4 + i;
        size_t idx = ((size_t)b * Sv + srow) * Ev + h * 64 + tx * 4;
        union { __nv_bfloat16 bb[4]; uint2 u; } uh, ul;
#pragma unroll
        for (int j = 0; j < 4; j++) {
            float v = ctx[i][j] * invl;
            uh.bb[j] = __float2bfloat16(v);
            ul.bb[j] = __float2bfloat16(v - __bfloat162float(uh.bb[j]));
        }
        *(uint2*)&g_ctxh[idx] = uh.u;
        *(uint2*)&g_ctxl[idx] = ul.u;
    }
}

// ---------------------------------------------------------------------------
extern "C" void kernel_launch(void* const* d_in, const int* in_sizes, int n_in,
                              void* d_out, int out_size)
{
    const float* query = (const float*)d_in[0];
    const float* key   = (const float*)d_in[1];
    const float* value = (const float*)d_in[2];
    const float* qkvw  = (const float*)d_in[3];
    const float* qkvb  = (const float*)d_in[4];
    const float* projw = (const float*)d_in[5];
    const float* projb = (const float*)d_in[6];
    const float* mask  = (const float*)d_in[7];
    float* out = (float*)d_out;

    // 1. fp32 -> bf16 hi/lo splits
    int n4x = Mv * Ev / 4;            // 1,048,576
    int n4w = 3 * Ev * Ev / 4;        //   786,432
    int n4p = Ev * Ev / 4;            //   262,144
    split_bf16<<<n4x / 256, 256>>>((const float4*)query, 0, n4x);
    split_bf16<<<n4x / 256, 256>>>((const float4*)key,   1, n4x);
    split_bf16<<<n4x / 256, 256>>>((const float4*)value, 2, n4x);
    split_bf16<<<n4w / 256, 256>>>((const float4*)qkvw,  3, n4w);
    split_bf16<<<n4p / 256, 256>>>((const float4*)projw, 4, n4p);

    // 2. HMMA QKV projection (double-buffered cp.async smem)
    size_t gsm = (size_t)2 * BSZ * sizeof(__nv_bfloat16);   // 81,920 B
    cudaFuncSetAttribute(gemm_mma<0>, cudaFuncAttributeMaxDynamicSharedMemorySize, (int)gsm);
    cudaFuncSetAttribute(gemm_mma<1>, cudaFuncAttributeMaxDynamicSharedMemorySize, (int)gsm);
    gemm_mma<0><<<dim3(Ev / TN, Mv / TM, 3), 256, gsm>>>(qkvb, nullptr);

    // 3. flash attention (fp32)
    size_t smem = (size_t)(64 * 64 + 64 * 65 + 64 * 64) * sizeof(float);
    cudaFuncSetAttribute(attn_kernel, cudaFuncAttributeMaxDynamicSharedMemorySize, (int)smem);
    attn_kernel<<<dim3(Sv / 64, Hv, Bv), 256, smem>>>(mask);

    // 4. HMMA output projection
    gemm_mma<1><<<dim3(Ev / TN, Mv / TM, 1), 256, gsm>>>(projb, out);
}